// round 17
// baseline (speedup 1.0000x reference)
#include <cuda_runtime.h>
#include <cstdint>

#define N_NODES    200000
#define N_CHILD    32
#define N_LAYERS   8
#define N_CHUNKS   4
#define CHUNK      50000          // floats per chunk: ~200KB smem
#define N_RANGES   37
#define RANGE_SZ   5408           // 37*5408 >= 200000, multiple of 8
#define THREADS    1024
#define STAGE_BYTES (CHUNK * 4)   // 200000 bytes, multiple of 16

// Ping-pong layer-value buffers (src/dst distinct — no grid sync in a launch).
__device__ float g_bufA[N_NODES];
__device__ float g_bufB[N_NODES];
// Per-chunk partial arrays: contiguous, single-writer cache lines.
__device__ float g_partial[N_CHUNKS][N_NODES];

__device__ __forceinline__ uint32_t smem_u32(const void* p) {
    uint32_t a;
    asm("{ .reg .u64 t; cvta.to.shared.u64 t, %1; cvt.u32.u64 %0, t; }"
        : "=r"(a) : "l"(p));
    return a;
}

// ---------------- Gather ----------------
// Grid = 37 ranges x 4 chunks = 148 blocks (one wave).
// Block (range,chunk): DMA-stages its 50K-float chunk into smem via one
// cp.async.bulk, plants a zero sentinel at sval[CHUNK], then computes the
// chunk's partial sum for every node of its range with UNPREDICATED LDS.
// Per child: r = (unsigned)(idx - cbase); r = umin(r, CHUNK)  — the ELEMENT
// index is clamped (both low-side underflow and high-side overflow land on
// the sentinel slot, contributing an exact +0.0f). NOTE: clamping the BYTE
// address instead is unsafe — smem bases are small, so low-side wraps can
// land just below sval and dodge the clamp (R16's NaN bug).
// 8 nodes/warp-task via two coalesced int4 loads per lane; 4-shfl butterfly
// reduction (merge A/B at xor-4, finish at xor-2/1).
__global__ void __launch_bounds__(THREADS, 1) gather_kernel(
    const float* __restrict__ src,     // layer-input values [N_NODES]
    const int4*  __restrict__ cidx)    // this layer's indices as int4
{
    extern __shared__ float sval[];    // CHUNK+1 floats (last = sentinel 0.0f)
    __shared__ __align__(8) unsigned long long s_mbar;

    const int chunk = blockIdx.x & (N_CHUNKS - 1);
    const int range = blockIdx.x >> 2;
    const int cbase = chunk * CHUNK;
    const int range_start = range * RANGE_SZ;

    // ---- Stage chunk via bulk async DMA ----
    const uint32_t mbar = smem_u32(&s_mbar);
    if (threadIdx.x == 0) {
        asm volatile("mbarrier.init.shared.b64 [%0], %1;"
                     :: "r"(mbar), "r"(1) : "memory");
    }
    __syncthreads();                   // init visible before anyone polls
    if (threadIdx.x == 0) {
        asm volatile("mbarrier.arrive.expect_tx.shared.b64 _, [%0], %1;"
                     :: "r"(mbar), "r"(STAGE_BYTES) : "memory");
        asm volatile(
            "cp.async.bulk.shared::cluster.global.mbarrier::complete_tx::bytes "
            "[%0], [%1], %2, [%3];"
            :: "r"(smem_u32(sval)), "l"(src + cbase),
               "r"(STAGE_BYTES), "r"(mbar) : "memory");
    }
    // Wait for DMA completion (phase 0).
    {
        uint32_t done;
        do {
            asm volatile(
                "{\n\t.reg .pred p;\n\t"
                "mbarrier.try_wait.parity.shared.b64 p, [%1], 0;\n\t"
                "selp.b32 %0, 1, 0, p;\n\t}"
                : "=r"(done) : "r"(mbar) : "memory");
        } while (!done);
    }
    // Plant sentinel, make visible to all threads before gathering.
    if (threadIdx.x == 0) sval[CHUNK] = 0.0f;
    __syncthreads();

    const uint32_t sval_u32 = smem_u32(sval);

    const int warp = threadIdx.x >> 5;
    const int lane = threadIdx.x & 31;

    // Branchless child gather: clamp ELEMENT index to the sentinel slot.
    auto gv = [&](int idx) -> float {
        uint32_t r = (uint32_t)(idx - cbase);          // wraps huge if idx<cbase
        r = (r < (uint32_t)CHUNK) ? r : (uint32_t)CHUNK;  // IMNMX.U32
        float v;
        asm("ld.shared.f32 %0, [%1];" : "=f"(v) : "r"(sval_u32 + (r << 2)));
        return v;
    };

    for (int t = warp; t * 8 < RANGE_SZ; t += THREADS / 32) {
        const int node0 = range_start + t * 8;
        if (node0 >= N_NODES) break;

        // Coalesced: lane k reads int4 k (nodes 0-3) and int4 32+k (nodes 4-7).
        const size_t ibase = (size_t)node0 * (N_CHILD / 4);
        const int4 cA = cidx[ibase + lane];
        const int4 cB = cidx[ibase + 32 + lane];

        const float sA = (gv(cA.x) + gv(cA.y)) + (gv(cA.z) + gv(cA.w));
        const float sB = (gv(cB.x) + gv(cB.y)) + (gv(cB.z) + gv(cB.w));

        // 4-shfl butterfly: lane g*8 ends with node A's sum, g*8+4 node B's.
        const float eA = __shfl_xor_sync(0xffffffffu, sA, 4);
        const float eB = __shfl_xor_sync(0xffffffffu, sB, 4);
        float v = (lane & 4) ? (sB + eB) : (sA + eA);
        v += __shfl_xor_sync(0xffffffffu, v, 2);
        v += __shfl_xor_sync(0xffffffffu, v, 1);

        if ((lane & 3) == 0)
            g_partial[chunk][node0 + (lane >> 3) + (lane & 4)] = v;
    }
}

// ---------------- Combine ----------------
__global__ void __launch_bounds__(256) combine_kernel(
    float*       __restrict__ dst,
    const int*   __restrict__ fids,    // this layer's fun_ids
    const float* __restrict__ wptr)
{
    const int n = blockIdx.x * blockDim.x + threadIdx.x;
    if (n >= N_NODES) return;

    const float s = (g_partial[0][n] + g_partial[1][n])
                  + (g_partial[2][n] + g_partial[3][n]);
    const float x = wptr[0] * s;
    const int fid = __ldg(fids + n);
    float r;
    if      (fid == 0) r = tanhf(x);
    else if (fid == 1) r = 1.0f / (1.0f + expf(-x));
    else if (fid == 2) r = fmaxf(x, 0.0f);
    else               r = x;
    dst[n] = r;
}

extern "C" void kernel_launch(void* const* d_in, const int* in_sizes, int n_in,
                              void* d_out, int out_size)
{
    const float* X    = (const float*)d_in[0];
    const float* w    = (const float*)d_in[1];
    const int*   cidx = (const int*)  d_in[2];  // [N_LAYERS, N_NODES, N_CHILD]
    const int*   fids = (const int*)  d_in[3];  // [N_LAYERS, N_NODES]
    float*       out  = (float*)d_out;

    float* bufA = nullptr;
    float* bufB = nullptr;
    cudaGetSymbolAddress((void**)&bufA, g_bufA);
    cudaGetSymbolAddress((void**)&bufB, g_bufB);

    const size_t SMEM_BYTES = ((size_t)CHUNK + 1) * sizeof(float); // +sentinel
    cudaFuncSetAttribute(gather_kernel,
                         cudaFuncAttributeMaxDynamicSharedMemorySize,
                         (int)SMEM_BYTES);

    // Ping-pong: layer i reads ins[i], writes outs[i] (always distinct).
    const float* ins[N_LAYERS]  = { X, bufA, bufB, bufA, bufB, bufA, bufB, bufA };
    float*       outs[N_LAYERS] = { bufA, bufB, bufA, bufB, bufA, bufB, bufA, out };

    const int gather_grid  = N_RANGES * N_CHUNKS;       // 148
    const int combine_grid = (N_NODES + 255) / 256;     // 782

    for (int l = 0; l < N_LAYERS; l++) {
        const int4* layer_cidx =
            (const int4*)(cidx + (size_t)l * N_NODES * N_CHILD);
        const int* layer_fids = fids + (size_t)l * N_NODES;

        gather_kernel<<<gather_grid, THREADS, SMEM_BYTES>>>(ins[l], layer_cidx);
        combine_kernel<<<combine_grid, 256>>>(outs[l], layer_fids, w);
    }
}